// round 14
// baseline (speedup 1.0000x reference)
#include <cuda_runtime.h>
#include <cuda_bf16.h>
#include <math.h>

#define NB 2
#define SEQ 2048
#define HID 2048
#define NHQ 16
#define NHKV 8
#define HD 128
#define WIN 1024
#define MROWS (NB*SEQ)   // 4096

// ---------------- scratch (static device globals; no cudaMalloc allowed) ----
__device__ float g_q[(size_t)MROWS * NHQ * HD];
__device__ float g_k[(size_t)MROWS * NHKV * HD];
__device__ float g_v[(size_t)MROWS * NHKV * HD];
__device__ float g_attn[(size_t)MROWS * NHQ * HD];
__device__ float g_rope_cos[SEQ * 64];
__device__ float g_rope_sin[SEQ * 64];
// pre-split bf16 buffers
__device__ __nv_bfloat16 g_h_hi[(size_t)MROWS * HID];
__device__ __nv_bfloat16 g_h_lo[(size_t)MROWS * HID];
__device__ __nv_bfloat16 g_wq_hi[(size_t)2048 * 2048];
__device__ __nv_bfloat16 g_wq_lo[(size_t)2048 * 2048];
__device__ __nv_bfloat16 g_wk_hi[(size_t)1024 * 2048];
__device__ __nv_bfloat16 g_wk_lo[(size_t)1024 * 2048];
__device__ __nv_bfloat16 g_wv_hi[(size_t)1024 * 2048];
__device__ __nv_bfloat16 g_wv_lo[(size_t)1024 * 2048];
__device__ __nv_bfloat16 g_wo_hi[(size_t)2048 * 2048];
__device__ __nv_bfloat16 g_wo_lo[(size_t)2048 * 2048];
__device__ __nv_bfloat16 g_at_hi[(size_t)MROWS * 2048];
__device__ __nv_bfloat16 g_at_lo[(size_t)MROWS * 2048];

// ---------------------------------------------------------------------------
__global__ void rope_table(float* __restrict__ ct, float* __restrict__ st)
{
    int idx = blockIdx.x * 256 + threadIdx.x;
    if (idx >= SEQ * 64) return;
    int pos = idx >> 6;
    int d   = idx & 63;
    double ang = (double)pos * pow(10000.0, -(double)d / 64.0);
    double s, c;
    sincos(ang, &s, &c);
    ct[idx] = (float)c;
    st[idx] = (float)s;
}

// ---------------------------------------------------------------------------
// helpers
// ---------------------------------------------------------------------------
__device__ __forceinline__ unsigned f2tf32(float x) {
    unsigned r;
    asm("cvt.rna.tf32.f32 %0, %1;" : "=r"(r) : "f"(x));
    return r;
}

__device__ __forceinline__ void mma_tf32(float c[4], const unsigned a[4],
                                         const unsigned b[2]) {
    asm volatile(
        "mma.sync.aligned.m16n8k8.row.col.f32.tf32.tf32.f32 "
        "{%0,%1,%2,%3}, {%4,%5,%6,%7}, {%8,%9}, {%0,%1,%2,%3};\n"
        : "+f"(c[0]), "+f"(c[1]), "+f"(c[2]), "+f"(c[3])
        : "r"(a[0]), "r"(a[1]), "r"(a[2]), "r"(a[3]), "r"(b[0]), "r"(b[1]));
}

__device__ __forceinline__ void mma_bf16(float c[4], const unsigned a[4],
                                         unsigned b0, unsigned b1) {
    asm volatile(
        "mma.sync.aligned.m16n8k16.row.col.f32.bf16.bf16.f32 "
        "{%0,%1,%2,%3}, {%4,%5,%6,%7}, {%8,%9}, {%0,%1,%2,%3};\n"
        : "+f"(c[0]), "+f"(c[1]), "+f"(c[2]), "+f"(c[3])
        : "r"(a[0]), "r"(a[1]), "r"(a[2]), "r"(a[3]), "r"(b0), "r"(b1));
}

__device__ __forceinline__ void ldsm4(unsigned r[4], unsigned addr) {
    asm volatile("ldmatrix.sync.aligned.m8n8.x4.shared.b16 {%0,%1,%2,%3}, [%4];"
        : "=r"(r[0]), "=r"(r[1]), "=r"(r[2]), "=r"(r[3]) : "r"(addr));
}

__device__ __forceinline__ unsigned pack_bf16(float a, float b) {
    unsigned r;
    asm("cvt.rn.bf16x2.f32 %0, %2, %1;" : "=r"(r) : "f"(a), "f"(b));
    return r;
}
__device__ __forceinline__ float trunc_hi(float x) {
    return __uint_as_float(__float_as_uint(x) & 0xFFFF0000u);
}

__device__ __forceinline__ void cpa16(unsigned dst, const void* src) {
    asm volatile("cp.async.cg.shared.global [%0], [%1], 16;" :: "r"(dst), "l"(src));
}
#define CPA_COMMIT() asm volatile("cp.async.commit_group;" ::: "memory")
#define CPA_WAIT1()  asm volatile("cp.async.wait_group 1;" ::: "memory")
#define CPA_WAIT0()  asm volatile("cp.async.wait_group 0;" ::: "memory")

// ---------------------------------------------------------------------------
// Split f32 -> bf16 hi/lo. BIT-IDENTICAL to R8's in-kernel split:
//   hi = truncation (byte_perm), lo = rn(x - trunc_hi(x)).
// ---------------------------------------------------------------------------
__global__ __launch_bounds__(256) void split_bf16(
    const float4* __restrict__ src, uint2* __restrict__ hi,
    uint2* __restrict__ lo, int n4)
{
    int i = blockIdx.x * 256 + threadIdx.x;
    if (i >= n4) return;
    float4 x = src[i];
    uint2 h, l;
    h.x = __byte_perm(__float_as_uint(x.x), __float_as_uint(x.y), 0x7632);
    h.y = __byte_perm(__float_as_uint(x.z), __float_as_uint(x.w), 0x7632);
    l.x = pack_bf16(x.x - trunc_hi(x.x), x.y - trunc_hi(x.y));
    l.y = pack_bf16(x.z - trunc_hi(x.z), x.w - trunc_hi(x.w));
    hi[i] = h;
    lo[i] = l;
}

// ---------------------------------------------------------------------------
// bf16 split-precision GEMM R14: pre-split operands streamed via cp.async
// (no LDG prefetch, no cvt, no STS). ldsm/mma/epilogue core = R8 exactly.
// ---------------------------------------------------------------------------
#define RSTR 48
#define TILE_B (128 * RSTR)
#define STG_B  (4 * TILE_B)
#define GEMM_SMEM (2 * STG_B)   // 49152

__device__ __forceinline__ void gemm_core(
    const __nv_bfloat16* __restrict__ Ah, const __nv_bfloat16* __restrict__ Al,
    const __nv_bfloat16* __restrict__ Bh, const __nv_bfloat16* __restrict__ Bl,
    float* __restrict__ C, int m0, int n0, int N, int K, char* gsm)
{
    unsigned sb;
    asm("{ .reg .u64 t; cvta.to.shared.u64 t, %1; cvt.u32.u64 %0, t; }"
        : "=r"(sb) : "l"(gsm));

    const int tid  = threadIdx.x;
    const int lane = tid & 31;
    const int warp = tid >> 5;
    const int wm = warp >> 1;
    const int wn = warp & 1;
    const int t  = lane & 3;

    // loader: row = tid>>1 (0..127), chunk = tid&1 (8 bf16 = 16B per chunk)
    const int lrow = tid >> 1;
    const int lc   = tid & 1;
    const unsigned so = (unsigned)(lrow * RSTR + (lc << 4));
    const __nv_bfloat16* AhR = Ah + (size_t)(m0 + lrow) * K + (lc << 3);
    const __nv_bfloat16* AlR = Al + (size_t)(m0 + lrow) * K + (lc << 3);
    const __nv_bfloat16* BhR = Bh + (size_t)(n0 + lrow) * K + (lc << 3);
    const __nv_bfloat16* BlR = Bl + (size_t)(n0 + lrow) * K + (lc << 3);

    const int sub = lane >> 3;
    const int rin = lane & 7;
    const unsigned a_off = (unsigned)(((sub & 1) * 8 + rin) * RSTR + (sub >> 1) * 16);
    const unsigned b_off = (unsigned)(((sub >> 1) * 8 + rin) * RSTR + (sub & 1) * 16);

    float acc[2][8][4] = {};
    const int nIter = K >> 4;

    auto issue = [&](int i) {
        unsigned stg = sb + (unsigned)(i & 1) * STG_B;
        int k0 = i << 4;
        cpa16(stg +            so, AhR + k0);
        cpa16(stg + TILE_B   + so, AlR + k0);
        cpa16(stg + 2*TILE_B + so, BhR + k0);
        cpa16(stg + 3*TILE_B + so, BlR + k0);
        CPA_COMMIT();
    };

    issue(0);

    for (int i = 0; i < nIter; i++) {
        if (i + 1 < nIter) { issue(i + 1); CPA_WAIT1(); }
        else               { CPA_WAIT0(); }
        __syncthreads();

        unsigned stg = sb + (unsigned)(i & 1) * STG_B;
        unsigned Ahi_b = stg + (unsigned)((wm << 5) * RSTR);
        unsigned Alo_b = Ahi_b + TILE_B;
        unsigned Bhi_b = stg + 2*TILE_B + (unsigned)((wn << 6) * RSTR);
        unsigned Blo_b = Bhi_b + TILE_B;

        unsigned ah[2][4], bh[4][4];
        #pragma unroll
        for (int mi = 0; mi < 2; mi++)
            ldsm4(ah[mi], Ahi_b + (unsigned)((mi << 4) * RSTR) + a_off);
        #pragma unroll
        for (int p = 0; p < 4; p++)
            ldsm4(bh[p], Bhi_b + (unsigned)((p << 4) * RSTR) + b_off);
        #pragma unroll
        for (int mi = 0; mi < 2; mi++)
            #pragma unroll
            for (int p = 0; p < 4; p++) {
                mma_bf16(acc[mi][(p<<1)  ], ah[mi], bh[p][0], bh[p][1]);
                mma_bf16(acc[mi][(p<<1)+1], ah[mi], bh[p][2], bh[p][3]);
            }
        unsigned al[2][4];
        #pragma unroll
        for (int mi = 0; mi < 2; mi++)
            ldsm4(al[mi], Alo_b + (unsigned)((mi << 4) * RSTR) + a_off);
        #pragma unroll
        for (int mi = 0; mi < 2; mi++)
            #pragma unroll
            for (int p = 0; p < 4; p++) {
                mma_bf16(acc[mi][(p<<1)  ], al[mi], bh[p][0], bh[p][1]);
                mma_bf16(acc[mi][(p<<1)+1], al[mi], bh[p][2], bh[p][3]);
            }
        unsigned bl[4][4];
        #pragma unroll
        for (int p = 0; p < 4; p++)
            ldsm4(bl[p], Blo_b + (unsigned)((p << 4) * RSTR) + b_off);
        #pragma unroll
        for (int mi = 0; mi < 2; mi++)
            #pragma unroll
            for (int p = 0; p < 4; p++) {
                mma_bf16(acc[mi][(p<<1)  ], ah[mi], bl[p][0], bl[p][1]);
                mma_bf16(acc[mi][(p<<1)+1], ah[mi], bl[p][2], bl[p][3]);
            }
        __syncthreads();   // compute on this stage done before it is refilled
    }

    const int gid = lane >> 2;
    #pragma unroll
    for (int mi = 0; mi < 2; mi++) {
        int r0 = m0 + (wm << 5) + (mi << 4) + gid;
        #pragma unroll
        for (int ni = 0; ni < 8; ni++) {
            int cc = n0 + (wn << 6) + (ni << 3) + (t << 1);
            *(float2*)(C + (size_t)r0 * N + cc) =
                make_float2(acc[mi][ni][0], acc[mi][ni][1]);
            *(float2*)(C + (size_t)(r0 + 8) * N + cc) =
                make_float2(acc[mi][ni][2], acc[mi][ni][3]);
        }
    }
}

// Fused QKV: grid (32 n-blocks, 32 m-blocks of 128 rows).
__global__ __launch_bounds__(256) void gemm_qkv(
    const __nv_bfloat16* __restrict__ hh, const __nv_bfloat16* __restrict__ hl,
    const __nv_bfloat16* __restrict__ qh, const __nv_bfloat16* __restrict__ ql,
    const __nv_bfloat16* __restrict__ kh, const __nv_bfloat16* __restrict__ kl,
    const __nv_bfloat16* __restrict__ vh, const __nv_bfloat16* __restrict__ vl,
    float* __restrict__ q, float* __restrict__ k, float* __restrict__ v)
{
    extern __shared__ __align__(16) char gsm[];
    int nb = blockIdx.x;
    int m0 = blockIdx.y << 7;
    const __nv_bfloat16 *Bh, *Bl; float* C; int N; int n0;
    if (nb < 16)      { Bh = qh; Bl = ql; C = q; N = NHQ*HD;  n0 = nb << 7; }
    else if (nb < 24) { Bh = kh; Bl = kl; C = k; N = NHKV*HD; n0 = (nb - 16) << 7; }
    else              { Bh = vh; Bl = vl; C = v; N = NHKV*HD; n0 = (nb - 24) << 7; }
    gemm_core(hh, hl, Bh, Bl, C, m0, n0, N, HID, gsm);
}

__global__ __launch_bounds__(256) void gemm_o(
    const __nv_bfloat16* __restrict__ ah, const __nv_bfloat16* __restrict__ al,
    const __nv_bfloat16* __restrict__ oh, const __nv_bfloat16* __restrict__ ol,
    float* __restrict__ C)
{
    extern __shared__ __align__(16) char gsm[];
    gemm_core(ah, al, oh, ol, C, blockIdx.y << 7, blockIdx.x << 7, HID, NHQ*HD, gsm);
}

// ---------------------------------------------------------------------------
// Fused RMSNorm + RoPE for BOTH q and k (unchanged).
// ---------------------------------------------------------------------------
__global__ __launch_bounds__(256) void norm_rope_both(
    float* __restrict__ xq, const float* __restrict__ wq,
    float* __restrict__ xk, const float* __restrict__ wk,
    const float* __restrict__ ct, const float* __restrict__ st)
{
    int gw   = (blockIdx.x * 256 + threadIdx.x) >> 5;
    int lane = threadIdx.x & 31;
    float* x; const float* w; int n_heads;
    if (gw < MROWS * NHQ) { x = xq; w = wq; n_heads = NHQ; }
    else { gw -= MROWS * NHQ; if (gw >= MROWS * NHKV) return;
           x = xk; w = wk; n_heads = NHKV; }
    int m = gw / n_heads;
    int h = gw - m * n_heads;
    int pos = m & (SEQ - 1);
    float* row = x + (size_t)m * (n_heads * HD) + h * HD;
    float x0 = row[lane], x1 = row[lane+32], x2 = row[lane+64], x3 = row[lane+96];
    float ss = x0*x0 + x1*x1 + x2*x2 + x3*x3;
    #pragma unroll
    for (int o = 16; o; o >>= 1) ss += __shfl_xor_sync(0xffffffffu, ss, o);
    float rstd = rsqrtf(ss * (1.0f / HD) + 1e-6f);
    float y0 = x0 * rstd * (1.f + w[lane]);
    float y1 = x1 * rstd * (1.f + w[lane+32]);
    float y2 = x2 * rstd * (1.f + w[lane+64]);
    float y3 = x3 * rstd * (1.f + w[lane+96]);
    float c0 = ct[pos*64 + lane],      s0 = st[pos*64 + lane];
    float c1 = ct[pos*64 + lane + 32], s1 = st[pos*64 + lane + 32];
    row[lane]      = y0 * c0 - y2 * s0;
    row[lane+64]   = y2 * c0 + y0 * s0;
    row[lane+32]   = y1 * c1 - y3 * s1;
    row[lane+96]   = y3 * c1 + y1 * s1;
}

// ---------------------------------------------------------------------------
// Flash attention — EXACT R8 version (302 us, 170 regs). FROZEN.
// ---------------------------------------------------------------------------
#define FBQ 128
#define FBK 64
#define QSTR 132
#define KSTR 72
#define VSTR 136
#define FLASH_WORDS (128*QSTR + 128*KSTR + 64*VSTR)
#define FLASH_BYTES (FLASH_WORDS * 4)

__global__ __launch_bounds__(256) void flash_tf32(
    const float* __restrict__ q, const float* __restrict__ k,
    const float* __restrict__ v, float* __restrict__ o)
{
    extern __shared__ unsigned smu[];
    unsigned* Qs  = smu;
    unsigned* KsT = Qs + 128 * QSTR;
    unsigned* Vs  = KsT + 128 * KSTR;

    const int tid  = threadIdx.x;
    const int lane = tid & 31;
    const int warp = tid >> 5;
    const int g    = lane >> 2;
    const int t    = lane & 3;
    const int mrow = warp << 4;

    const int q0 = blockIdx.x * FBQ;
    const int h  = blockIdx.y;
    const int b  = blockIdx.z;
    const int hk = h >> 1;
    const float* qbase = q + (size_t)b * SEQ * (NHQ  * HD) + h  * HD;
    const float* kbase = k + (size_t)b * SEQ * (NHKV * HD) + hk * HD;
    const float* vbase = v + (size_t)b * SEQ * (NHKV * HD) + hk * HD;
    const float scale = 0.08838834764831845f;

    #pragma unroll
    for (int rep = 0; rep < 16; rep++) {
        int idx = rep * 256 + tid;
        int r   = idx >> 5;
        int dc  = (idx & 31) << 2;
        float4 va = *(const float4*)(qbase + (size_t)(q0 + r) * (NHQ * HD) + dc);
        unsigned* dst = Qs + r * QSTR + dc;
        dst[0] = f2tf32(va.x * scale); dst[1] = f2tf32(va.y * scale);
        dst[2] = f2tf32(va.z * scale); dst[3] = f2tf32(va.w * scale);
    }

    float oacc[16][4] = {};
    float m_lo = -1e30f, m_hi = -1e30f, l_lo = 0.f, l_hi = 0.f;
    const int qi_lo = q0 + mrow + g;
    const int qi_hi = qi_lo + 8;

    int jlo = q0 - (WIN - 1); if (jlo < 0) jlo = 0;
    const int jstart = jlo & ~(FBK - 1);

    const int src0 = (lane & ~3) | (t >> 1);
    const int src1 = src0 + 2;
    const bool odd = t & 1;

    for (int j0 = jstart; j0 < q0 + FBQ; j0 += FBK) {
        __syncthreads();
        {
            int r  = tid >> 2;
            int c4 = (tid & 3) << 2;
            #pragma unroll
            for (int sub2 = 0; sub2 < 8; sub2++) {
                float4 kv = *(const float4*)(kbase + (size_t)(j0 + r) * (NHKV * HD) + sub2 * 16 + c4);
                int dbase = sub2 * 16 + c4;
                KsT[(dbase+0)*KSTR + r] = f2tf32(kv.x);
                KsT[(dbase+1)*KSTR + r] = f2tf32(kv.y);
                KsT[(dbase+2)*KSTR + r] = f2tf32(kv.z);
                KsT[(dbase+3)*KSTR + r] = f2tf32(kv.w);
            }
        }
        #pragma unroll
        for (int rep = 0; rep < 8; rep++) {
            int idx = rep * 256 + tid;
            int r   = idx >> 5;
            int dc  = (idx & 31) << 2;
            float4 vv = *(const float4*)(vbase + (size_t)(j0 + r) * (NHKV * HD) + dc);
            unsigned* dst = Vs + r * VSTR + dc;
            dst[0] = f2tf32(vv.x); dst[1] = f2tf32(vv.y);
            dst[2] = f2tf32(vv.z); dst[3] = f2tf32(vv.w);
        }
        __syncthreads();

        float sacc[8][4] = {};
        #pragma unroll
        for (int kc = 0; kc < 16; kc++) {
            int kb = kc << 3;
            unsigned qa[4];
            qa[0] = Qs[(mrow + g    ) * QSTR + kb + t];
            qa[1] = Qs[(mrow + g + 8) * QSTR + kb + t];
            qa[2] = Qs[(mrow + g    ) * QSTR + kb + t + 4];
            qa[3] = Qs[(mrow + g + 8) * QSTR + kb + t + 4];
            unsigned bb[8][2];
            #pragma unroll
            for (int ni = 0; ni < 8; ni++) {
                bb[ni][0] = KsT[(kb + t    ) * KSTR + (ni << 3) + g];
                bb[ni][1] = KsT[(kb + t + 4) * KSTR + (ni << 3) + g];
            }
            #pragma unroll
            for (int ni = 0; ni < 8; ni++)
                mma_tf32(sacc[ni], qa, bb[ni]);
        }

        float mx_lo = -1e30f, mx_hi = -1e30f;
        #pragma unroll
        for (int ni = 0; ni < 8; ni++) {
            int c0 = j0 + (ni << 3) + (t << 1);
            int c1 = c0 + 1;
            if (!((c0 <= qi_lo) && (c0 > qi_lo - WIN))) sacc[ni][0] = -1e30f;
            if (!((c1 <= qi_lo) && (c1 > qi_lo - WIN))) sacc[ni][1] = -1e30f;
            if (!((c0 <= qi_hi) && (c0 > qi_hi - WIN))) sacc[ni][2] = -1e30f;
            if (!((c1 <= qi_hi) && (c1 > qi_hi - WIN))) sacc[ni][3] = -1e30f;
            mx_lo = fmaxf(mx_lo, fmaxf(sacc[ni][0], sacc[ni][1]));
            mx_hi = fmaxf(mx_hi, fmaxf(sacc[ni][2], sacc[ni][3]));
        }
        mx_lo = fmaxf(mx_lo, __shfl_xor_sync(0xffffffffu, mx_lo, 1));
        mx_lo = fmaxf(mx_lo, __shfl_xor_sync(0xffffffffu, mx_lo, 2));
        mx_hi = fmaxf(mx_hi, __shfl_xor_sync(0xffffffffu, mx_hi, 1));
        mx_hi = fmaxf(mx_hi, __shfl_xor_sync(0xffffffffu, mx_hi, 2));

        float mnl = fmaxf(m_lo, mx_lo);
        float mnh = fmaxf(m_hi, mx_hi);
        float cl  = __expf(m_lo - mnl);
        float ch  = __expf(m_hi - mnh);
        m_lo = mnl; m_hi = mnh;

        float ps_lo = 0.f, ps_hi = 0.f;
        unsigned pf[8][4];
        #pragma unroll
        for (int ni = 0; ni < 8; ni++) {
            float p0 = (sacc[ni][0] > -1e29f) ? __expf(sacc[ni][0] - mnl) : 0.f;
            float p1 = (sacc[ni][1] > -1e29f) ? __expf(sacc[ni][1] - mnl) : 0.f;
            float p2 = (sacc[ni][2] > -1e29f) ? __expf(sacc[ni][2] - mnh) : 0.f;
            float p3 = (sacc[ni][3] > -1e29f) ? __expf(sacc[ni][3] - mnh) : 0.f;
            ps_lo += p0 + p1;
            ps_hi += p2 + p3;
            pf[ni][0] = f2tf32(p0); pf[ni][1] = f2tf32(p1);
            pf[ni][2] = f2tf32(p2); pf[ni][3] = f2tf32(p3);
        }
        ps_lo += __shfl_xor_sync(0xffffffffu, ps_lo, 1);
        ps_lo += __shfl_xor_sync(0xffffffffu, ps_lo, 2);
        ps_hi += __shfl_xor_sync(0xffffffffu, ps_hi, 1);
        ps_hi += __shfl_xor_sync(0xffffffffu, ps_hi, 2);
        l_lo = l_lo * cl + ps_lo;
        l_hi = l_hi * ch + ps_hi;

        #pragma unroll
        for (int n2 = 0; n2 < 16; n2++) {
            oacc[n2][0] *= cl; oacc[n2][1] *= cl;
            oacc[n2][2] *= ch; oacc[n2][3] *= ch;
        }

        #pragma unroll
        for (int kc = 0; kc < 8; kc++) {
            unsigned e0 = __shfl_sync(0xffffffffu, pf[kc][0], src0);
            unsigned o0 = __shfl_sync(0xffffffffu, pf[kc][1], src0);
            unsigned e1 = __shfl_sync(0xffffffffu, pf[kc][0], src1);
            unsigned o1 = __shfl_sync(0xffffffffu, pf[kc][1], src1);
            unsigned e2 = __shfl_sync(0xffffffffu, pf[kc][2], src0);
            unsigned o2 = __shfl_sync(0xffffffffu, pf[kc][3], src0);
            unsigned e3 = __shfl_sync(0xffffffffu, pf[kc][2], src1);
            unsigned o3 = __shfl_sync(0xffffffffu, pf[kc][3], src1);
            unsigned af[4];
            af[0] = odd ? o0 : e0;
            af[1] = odd ? o2 : e2;
            af[2] = odd ? o1 : e1;
            af[3] = odd ? o3 : e3;
            int kb = kc << 3;
            #pragma unroll
            for (int n2 = 0; n2 < 16; n2++) {
                unsigned bb2[2];
                bb2[0] = Vs[(kb + t    ) * VSTR + (n2 << 3) + g];
                bb2[1] = Vs[(kb + t + 4) * VSTR + (n2 << 3) + g];
                mma_tf32(oacc[n2], af, bb2);
            }
        }
    }

    float il = 1.0f / l_lo;
    float ih = 1.0f / l_hi;
    float* obase = o + (size_t)b * SEQ * (NHQ * HD) + h * HD;
    int rlo = q0 + mrow + g;
    int rhi = rlo + 8;
    #pragma unroll
    for (int n2 = 0; n2 < 16; n2++) {
        int dn = (n2 << 3) + (t << 1);
        *(float2*)(obase + (size_t)rlo * (NHQ * HD) + dn) =
            make_float2(oacc[n2][0] * il, oacc[n2][1] * il);
        *(float2*)(obase + (size_t)rhi * (NHQ * HD) + dn) =
            make_float2(oacc[n2][2] * ih, oacc[n2][3] * ih);
    }
}

// ---------------------------------------------------------------------------
extern "C" void kernel_launch(void* const* d_in, const int* in_sizes, int n_in,
                              void* d_out, int out_size)
{
    const float* hidden = (const float*)d_in[0];
    const float* wq = (const float*)d_in[1];
    const float* wk = (const float*)d_in[2];
    const float* wv = (const float*)d_in[3];
    const float* wo = (const float*)d_in[4];
    const float* qw = (const float*)d_in[5];
    const float* kw = (const float*)d_in[6];
    float* out = (float*)d_out;

    float *q, *k, *v, *attn, *ct, *st;
    cudaGetSymbolAddress((void**)&q,    g_q);
    cudaGetSymbolAddress((void**)&k,    g_k);
    cudaGetSymbolAddress((void**)&v,    g_v);
    cudaGetSymbolAddress((void**)&attn, g_attn);
    cudaGetSymbolAddress((void**)&ct,   g_rope_cos);
    cudaGetSymbolAddress((void**)&st,   g_rope_sin);
    __nv_bfloat16 *hh, *hl, *qh, *ql, *kh, *kl, *vh, *vl, *oh, *ol, *ah, *al;
    cudaGetSymbolAddress((void**)&hh, g_h_hi);  cudaGetSymbolAddress((void**)&hl, g_h_lo);
    cudaGetSymbolAddress((void**)&qh, g_wq_hi); cudaGetSymbolAddress((void**)&ql, g_wq_lo);
    cudaGetSymbolAddress((void**)&kh, g_wk_hi); cudaGetSymbolAddress((void**)&kl, g_wk_lo);
    cudaGetSymbolAddress((void**)&vh, g_wv_hi); cudaGetSymbolAddress((void**)&vl, g_wv_lo);
    cudaGetSymbolAddress((void**)&oh, g_wo_hi); cudaGetSymbolAddress((void**)&ol, g_wo_lo);
    cudaGetSymbolAddress((void**)&ah, g_at_hi); cudaGetSymbolAddress((void**)&al, g_at_lo);

    cudaFuncSetAttribute(flash_tf32, cudaFuncAttributeMaxDynamicSharedMemorySize,
                         FLASH_BYTES);
    cudaFuncSetAttribute(gemm_qkv, cudaFuncAttributeMaxDynamicSharedMemorySize,
                         GEMM_SMEM);
    cudaFuncSetAttribute(gemm_o, cudaFuncAttributeMaxDynamicSharedMemorySize,
                         GEMM_SMEM);

    rope_table<<<(SEQ*64 + 255) / 256, 256>>>(ct, st);

    // pre-split inputs (bit-identical to R8's in-kernel split)
    int nh4 = (MROWS * HID) / 4;
    split_bf16<<<nh4/256, 256>>>((const float4*)hidden, (uint2*)hh, (uint2*)hl, nh4);
    int nq4 = (2048 * 2048) / 4;
    split_bf16<<<nq4/256, 256>>>((const float4*)wq, (uint2*)qh, (uint2*)ql, nq4);
    int nk4 = (1024 * 2048) / 4;
    split_bf16<<<nk4/256, 256>>>((const float4*)wk, (uint2*)kh, (uint2*)kl, nk4);
    split_bf16<<<nk4/256, 256>>>((const float4*)wv, (uint2*)vh, (uint2*)vl, nk4);
    split_bf16<<<nq4/256, 256>>>((const float4*)wo, (uint2*)oh, (uint2*)ol, nq4);

    // fused QKV projection (cp.async, pre-split operands)
    gemm_qkv<<<dim3(32, MROWS/128), 256, GEMM_SMEM>>>(hh, hl, qh, ql, kh, kl, vh, vl, q, k, v);

    // fused norm+rope
    {
        int warps = MROWS * (NHQ + NHKV);
        norm_rope_both<<<(warps*32 + 255) / 256, 256>>>(q, qw, k, kw, ct, st);
    }

    // flash attention (R8 frozen)
    flash_tf32<<<dim3(SEQ/FBQ, NHQ, NB), 256, FLASH_BYTES>>>(q, k, v, attn);

    // split attn, then O projection
    int na4 = (MROWS * 2048) / 4;
    split_bf16<<<na4/256, 256>>>((const float4*)attn, (uint2*)ah, (uint2*)al, na4);
    gemm_o<<<dim3(HID/128, MROWS/128), 256, GEMM_SMEM>>>(ah, al, oh, ol, out);
}

// round 15
// speedup vs baseline: 1.0499x; 1.0499x over previous
#include <cuda_runtime.h>
#include <cuda_bf16.h>
#include <math.h>

#define NB 2
#define SEQ 2048
#define HID 2048
#define NHQ 16
#define NHKV 8
#define HD 128
#define WIN 1024
#define MROWS (NB*SEQ)   // 4096

// ---------------- scratch (static device globals; no cudaMalloc allowed) ----
__device__ float g_q[(size_t)MROWS * NHQ * HD];
__device__ float g_k[(size_t)MROWS * NHKV * HD];
__device__ float g_v[(size_t)MROWS * NHKV * HD];
__device__ float g_attn[(size_t)MROWS * NHQ * HD];
__device__ float g_rope_cos[SEQ * 64];
__device__ float g_rope_sin[SEQ * 64];
// pre-split bf16 buffers
__device__ __nv_bfloat16 g_h_hi[(size_t)MROWS * HID];
__device__ __nv_bfloat16 g_h_lo[(size_t)MROWS * HID];
__device__ __nv_bfloat16 g_wq_hi[(size_t)2048 * 2048];
__device__ __nv_bfloat16 g_wq_lo[(size_t)2048 * 2048];
__device__ __nv_bfloat16 g_wk_hi[(size_t)1024 * 2048];
__device__ __nv_bfloat16 g_wk_lo[(size_t)1024 * 2048];
__device__ __nv_bfloat16 g_wv_hi[(size_t)1024 * 2048];
__device__ __nv_bfloat16 g_wv_lo[(size_t)1024 * 2048];
__device__ __nv_bfloat16 g_wo_hi[(size_t)2048 * 2048];
__device__ __nv_bfloat16 g_wo_lo[(size_t)2048 * 2048];
__device__ __nv_bfloat16 g_at_hi[(size_t)MROWS * 2048];
__device__ __nv_bfloat16 g_at_lo[(size_t)MROWS * 2048];

// ---------------------------------------------------------------------------
__global__ void rope_table(float* __restrict__ ct, float* __restrict__ st)
{
    int idx = blockIdx.x * 256 + threadIdx.x;
    if (idx >= SEQ * 64) return;
    int pos = idx >> 6;
    int d   = idx & 63;
    double ang = (double)pos * pow(10000.0, -(double)d / 64.0);
    double s, c;
    sincos(ang, &s, &c);
    ct[idx] = (float)c;
    st[idx] = (float)s;
}

// ---------------------------------------------------------------------------
// helpers
// ---------------------------------------------------------------------------
__device__ __forceinline__ unsigned f2tf32(float x) {
    unsigned r;
    asm("cvt.rna.tf32.f32 %0, %1;" : "=r"(r) : "f"(x));
    return r;
}

__device__ __forceinline__ void mma_tf32(float c[4], const unsigned a[4],
                                         const unsigned b[2]) {
    asm volatile(
        "mma.sync.aligned.m16n8k8.row.col.f32.tf32.tf32.f32 "
        "{%0,%1,%2,%3}, {%4,%5,%6,%7}, {%8,%9}, {%0,%1,%2,%3};\n"
        : "+f"(c[0]), "+f"(c[1]), "+f"(c[2]), "+f"(c[3])
        : "r"(a[0]), "r"(a[1]), "r"(a[2]), "r"(a[3]), "r"(b[0]), "r"(b[1]));
}

__device__ __forceinline__ void mma_bf16(float c[4], const unsigned a[4],
                                         unsigned b0, unsigned b1) {
    asm volatile(
        "mma.sync.aligned.m16n8k16.row.col.f32.bf16.bf16.f32 "
        "{%0,%1,%2,%3}, {%4,%5,%6,%7}, {%8,%9}, {%0,%1,%2,%3};\n"
        : "+f"(c[0]), "+f"(c[1]), "+f"(c[2]), "+f"(c[3])
        : "r"(a[0]), "r"(a[1]), "r"(a[2]), "r"(a[3]), "r"(b0), "r"(b1));
}

__device__ __forceinline__ void ldsm4(unsigned r[4], unsigned addr) {
    asm volatile("ldmatrix.sync.aligned.m8n8.x4.shared.b16 {%0,%1,%2,%3}, [%4];"
        : "=r"(r[0]), "=r"(r[1]), "=r"(r[2]), "=r"(r[3]) : "r"(addr));
}

__device__ __forceinline__ unsigned pack_bf16(float a, float b) {
    unsigned r;
    asm("cvt.rn.bf16x2.f32 %0, %2, %1;" : "=r"(r) : "f"(a), "f"(b));
    return r;
}
__device__ __forceinline__ float trunc_hi(float x) {
    return __uint_as_float(__float_as_uint(x) & 0xFFFF0000u);
}

__device__ __forceinline__ void cpa16(unsigned dst, const void* src) {
    asm volatile("cp.async.cg.shared.global [%0], [%1], 16;" :: "r"(dst), "l"(src));
}
#define CPA_COMMIT() asm volatile("cp.async.commit_group;" ::: "memory")
#define CPA_WAIT2()  asm volatile("cp.async.wait_group 2;" ::: "memory")
#define CPA_WAIT1()  asm volatile("cp.async.wait_group 1;" ::: "memory")
#define CPA_WAIT0()  asm volatile("cp.async.wait_group 0;" ::: "memory")

// ---------------------------------------------------------------------------
// Split f32 -> bf16 hi/lo (bit-identical to R8's in-kernel split; validated R14)
// ---------------------------------------------------------------------------
__global__ __launch_bounds__(256) void split_bf16(
    const float4* __restrict__ src, uint2* __restrict__ hi,
    uint2* __restrict__ lo, int n4)
{
    int i = blockIdx.x * 256 + threadIdx.x;
    if (i >= n4) return;
    float4 x = src[i];
    uint2 h, l;
    h.x = __byte_perm(__float_as_uint(x.x), __float_as_uint(x.y), 0x7632);
    h.y = __byte_perm(__float_as_uint(x.z), __float_as_uint(x.w), 0x7632);
    l.x = pack_bf16(x.x - trunc_hi(x.x), x.y - trunc_hi(x.y));
    l.y = pack_bf16(x.z - trunc_hi(x.z), x.w - trunc_hi(x.w));
    hi[i] = h;
    lo[i] = l;
}

// ---------------------------------------------------------------------------
// bf16 split-precision GEMM R15: pre-split operands, cp.async, **3-stage
// pipeline, ONE barrier per iter** (wait_group 2 => each group gets 2 compute
// phases to land). ldsm/mma/epilogue core = R8 exactly.
// ---------------------------------------------------------------------------
#define RSTR 48
#define TILE_B (128 * RSTR)
#define STG_B  (4 * TILE_B)
#define GEMM_SMEM (3 * STG_B)   // 73728

__device__ __forceinline__ void gemm_core(
    const __nv_bfloat16* __restrict__ Ah, const __nv_bfloat16* __restrict__ Al,
    const __nv_bfloat16* __restrict__ Bh, const __nv_bfloat16* __restrict__ Bl,
    float* __restrict__ C, int m0, int n0, int N, int K, char* gsm)
{
    unsigned sb;
    asm("{ .reg .u64 t; cvta.to.shared.u64 t, %1; cvt.u32.u64 %0, t; }"
        : "=r"(sb) : "l"(gsm));

    const int tid  = threadIdx.x;
    const int lane = tid & 31;
    const int warp = tid >> 5;
    const int wm = warp >> 1;
    const int wn = warp & 1;
    const int t  = lane & 3;

    // loader: row = tid>>1 (0..127), chunk = tid&1 (8 bf16 = 16B per chunk)
    const int lrow = tid >> 1;
    const int lc   = tid & 1;
    const unsigned so = (unsigned)(lrow * RSTR + (lc << 4));
    const __nv_bfloat16* AhR = Ah + (size_t)(m0 + lrow) * K + (lc << 3);
    const __nv_bfloat16* AlR = Al + (size_t)(m0 + lrow) * K + (lc << 3);
    const __nv_bfloat16* BhR = Bh + (size_t)(n0 + lrow) * K + (lc << 3);
    const __nv_bfloat16* BlR = Bl + (size_t)(n0 + lrow) * K + (lc << 3);

    const int sub = lane >> 3;
    const int rin = lane & 7;
    const unsigned a_off = (unsigned)(((sub & 1) * 8 + rin) * RSTR + (sub >> 1) * 16);
    const unsigned b_off = (unsigned)(((sub >> 1) * 8 + rin) * RSTR + (sub & 1) * 16);

    float acc[2][8][4] = {};
    const int nIter = K >> 4;

    auto issue = [&](int i) {
        unsigned stg = sb + (unsigned)(i % 3) * STG_B;
        int k0 = i << 4;
        cpa16(stg +            so, AhR + k0);
        cpa16(stg + TILE_B   + so, AlR + k0);
        cpa16(stg + 2*TILE_B + so, BhR + k0);
        cpa16(stg + 3*TILE_B + so, BlR + k0);
        CPA_COMMIT();
    };

    issue(0);
    issue(1);

    for (int i = 0; i < nIter; i++) {
        __syncthreads();                 // all warps done computing stage i-1
        if (i + 2 < nIter) { issue(i + 2); CPA_WAIT2(); }
        else if (i + 1 < nIter) { CPA_WAIT1(); }
        else { CPA_WAIT0(); }

        unsigned stg = sb + (unsigned)(i % 3) * STG_B;
        unsigned Ahi_b = stg + (unsigned)((wm << 5) * RSTR);
        unsigned Alo_b = Ahi_b + TILE_B;
        unsigned Bhi_b = stg + 2*TILE_B + (unsigned)((wn << 6) * RSTR);
        unsigned Blo_b = Bhi_b + TILE_B;

        unsigned ah[2][4], bh[4][4];
        #pragma unroll
        for (int mi = 0; mi < 2; mi++)
            ldsm4(ah[mi], Ahi_b + (unsigned)((mi << 4) * RSTR) + a_off);
        #pragma unroll
        for (int p = 0; p < 4; p++)
            ldsm4(bh[p], Bhi_b + (unsigned)((p << 4) * RSTR) + b_off);
        #pragma unroll
        for (int mi = 0; mi < 2; mi++)
            #pragma unroll
            for (int p = 0; p < 4; p++) {
                mma_bf16(acc[mi][(p<<1)  ], ah[mi], bh[p][0], bh[p][1]);
                mma_bf16(acc[mi][(p<<1)+1], ah[mi], bh[p][2], bh[p][3]);
            }
        unsigned al[2][4];
        #pragma unroll
        for (int mi = 0; mi < 2; mi++)
            ldsm4(al[mi], Alo_b + (unsigned)((mi << 4) * RSTR) + a_off);
        #pragma unroll
        for (int mi = 0; mi < 2; mi++)
            #pragma unroll
            for (int p = 0; p < 4; p++) {
                mma_bf16(acc[mi][(p<<1)  ], al[mi], bh[p][0], bh[p][1]);
                mma_bf16(acc[mi][(p<<1)+1], al[mi], bh[p][2], bh[p][3]);
            }
        unsigned bl[4][4];
        #pragma unroll
        for (int p = 0; p < 4; p++)
            ldsm4(bl[p], Blo_b + (unsigned)((p << 4) * RSTR) + b_off);
        #pragma unroll
        for (int mi = 0; mi < 2; mi++)
            #pragma unroll
            for (int p = 0; p < 4; p++) {
                mma_bf16(acc[mi][(p<<1)  ], ah[mi], bl[p][0], bl[p][1]);
                mma_bf16(acc[mi][(p<<1)+1], ah[mi], bl[p][2], bl[p][3]);
            }
    }

    const int gid = lane >> 2;
    #pragma unroll
    for (int mi = 0; mi < 2; mi++) {
        int r0 = m0 + (wm << 5) + (mi << 4) + gid;
        #pragma unroll
        for (int ni = 0; ni < 8; ni++) {
            int cc = n0 + (wn << 6) + (ni << 3) + (t << 1);
            *(float2*)(C + (size_t)r0 * N + cc) =
                make_float2(acc[mi][ni][0], acc[mi][ni][1]);
            *(float2*)(C + (size_t)(r0 + 8) * N + cc) =
                make_float2(acc[mi][ni][2], acc[mi][ni][3]);
        }
    }
}

// Fused QKV: grid (32 n-blocks, 32 m-blocks of 128 rows).
__global__ __launch_bounds__(256) void gemm_qkv(
    const __nv_bfloat16* __restrict__ hh, const __nv_bfloat16* __restrict__ hl,
    const __nv_bfloat16* __restrict__ qh, const __nv_bfloat16* __restrict__ ql,
    const __nv_bfloat16* __restrict__ kh, const __nv_bfloat16* __restrict__ kl,
    const __nv_bfloat16* __restrict__ vh, const __nv_bfloat16* __restrict__ vl,
    float* __restrict__ q, float* __restrict__ k, float* __restrict__ v)
{
    extern __shared__ __align__(16) char gsm[];
    int nb = blockIdx.x;
    int m0 = blockIdx.y << 7;
    const __nv_bfloat16 *Bh, *Bl; float* C; int N; int n0;
    if (nb < 16)      { Bh = qh; Bl = ql; C = q; N = NHQ*HD;  n0 = nb << 7; }
    else if (nb < 24) { Bh = kh; Bl = kl; C = k; N = NHKV*HD; n0 = (nb - 16) << 7; }
    else              { Bh = vh; Bl = vl; C = v; N = NHKV*HD; n0 = (nb - 24) << 7; }
    gemm_core(hh, hl, Bh, Bl, C, m0, n0, N, HID, gsm);
}

__global__ __launch_bounds__(256) void gemm_o(
    const __nv_bfloat16* __restrict__ ah, const __nv_bfloat16* __restrict__ al,
    const __nv_bfloat16* __restrict__ oh, const __nv_bfloat16* __restrict__ ol,
    float* __restrict__ C)
{
    extern __shared__ __align__(16) char gsm[];
    gemm_core(ah, al, oh, ol, C, blockIdx.y << 7, blockIdx.x << 7, HID, NHQ*HD, gsm);
}

// ---------------------------------------------------------------------------
// Fused RMSNorm + RoPE for BOTH q and k (unchanged).
// ---------------------------------------------------------------------------
__global__ __launch_bounds__(256) void norm_rope_both(
    float* __restrict__ xq, const float* __restrict__ wq,
    float* __restrict__ xk, const float* __restrict__ wk,
    const float* __restrict__ ct, const float* __restrict__ st)
{
    int gw   = (blockIdx.x * 256 + threadIdx.x) >> 5;
    int lane = threadIdx.x & 31;
    float* x; const float* w; int n_heads;
    if (gw < MROWS * NHQ) { x = xq; w = wq; n_heads = NHQ; }
    else { gw -= MROWS * NHQ; if (gw >= MROWS * NHKV) return;
           x = xk; w = wk; n_heads = NHKV; }
    int m = gw / n_heads;
    int h = gw - m * n_heads;
    int pos = m & (SEQ - 1);
    float* row = x + (size_t)m * (n_heads * HD) + h * HD;
    float x0 = row[lane], x1 = row[lane+32], x2 = row[lane+64], x3 = row[lane+96];
    float ss = x0*x0 + x1*x1 + x2*x2 + x3*x3;
    #pragma unroll
    for (int o = 16; o; o >>= 1) ss += __shfl_xor_sync(0xffffffffu, ss, o);
    float rstd = rsqrtf(ss * (1.0f / HD) + 1e-6f);
    float y0 = x0 * rstd * (1.f + w[lane]);
    float y1 = x1 * rstd * (1.f + w[lane+32]);
    float y2 = x2 * rstd * (1.f + w[lane+64]);
    float y3 = x3 * rstd * (1.f + w[lane+96]);
    float c0 = ct[pos*64 + lane],      s0 = st[pos*64 + lane];
    float c1 = ct[pos*64 + lane + 32], s1 = st[pos*64 + lane + 32];
    row[lane]      = y0 * c0 - y2 * s0;
    row[lane+64]   = y2 * c0 + y0 * s0;
    row[lane+32]   = y1 * c1 - y3 * s1;
    row[lane+96]   = y3 * c1 + y1 * s1;
}

// ---------------------------------------------------------------------------
// Flash attention — EXACT R8 version (302 us, 170 regs). FROZEN.
// ---------------------------------------------------------------------------
#define FBQ 128
#define FBK 64
#define QSTR 132
#define KSTR 72
#define VSTR 136
#define FLASH_WORDS (128*QSTR + 128*KSTR + 64*VSTR)
#define FLASH_BYTES (FLASH_WORDS * 4)

__global__ __launch_bounds__(256) void flash_tf32(
    const float* __restrict__ q, const float* __restrict__ k,
    const float* __restrict__ v, float* __restrict__ o)
{
    extern __shared__ unsigned smu[];
    unsigned* Qs  = smu;
    unsigned* KsT = Qs + 128 * QSTR;
    unsigned* Vs  = KsT + 128 * KSTR;

    const int tid  = threadIdx.x;
    const int lane = tid & 31;
    const int warp = tid >> 5;
    const int g    = lane >> 2;
    const int t    = lane & 3;
    const int mrow = warp << 4;

    const int q0 = blockIdx.x * FBQ;
    const int h  = blockIdx.y;
    const int b  = blockIdx.z;
    const int hk = h >> 1;
    const float* qbase = q + (size_t)b * SEQ * (NHQ  * HD) + h  * HD;
    const float* kbase = k + (size_t)b * SEQ * (NHKV * HD) + hk * HD;
    const float* vbase = v + (size_t)b * SEQ * (NHKV * HD) + hk * HD;
    const float scale = 0.08838834764831845f;

    #pragma unroll
    for (int rep = 0; rep < 16; rep++) {
        int idx = rep * 256 + tid;
        int r   = idx >> 5;
        int dc  = (idx & 31) << 2;
        float4 va = *(const float4*)(qbase + (size_t)(q0 + r) * (NHQ * HD) + dc);
        unsigned* dst = Qs + r * QSTR + dc;
        dst[0] = f2tf32(va.x * scale); dst[1] = f2tf32(va.y * scale);
        dst[2] = f2tf32(va.z * scale); dst[3] = f2tf32(va.w * scale);
    }

    float oacc[16][4] = {};
    float m_lo = -1e30f, m_hi = -1e30f, l_lo = 0.f, l_hi = 0.f;
    const int qi_lo = q0 + mrow + g;
    const int qi_hi = qi_lo + 8;

    int jlo = q0 - (WIN - 1); if (jlo < 0) jlo = 0;
    const int jstart = jlo & ~(FBK - 1);

    const int src0 = (lane & ~3) | (t >> 1);
    const int src1 = src0 + 2;
    const bool odd = t & 1;

    for (int j0 = jstart; j0 < q0 + FBQ; j0 += FBK) {
        __syncthreads();
        {
            int r  = tid >> 2;
            int c4 = (tid & 3) << 2;
            #pragma unroll
            for (int sub2 = 0; sub2 < 8; sub2++) {
                float4 kv = *(const float4*)(kbase + (size_t)(j0 + r) * (NHKV * HD) + sub2 * 16 + c4);
                int dbase = sub2 * 16 + c4;
                KsT[(dbase+0)*KSTR + r] = f2tf32(kv.x);
                KsT[(dbase+1)*KSTR + r] = f2tf32(kv.y);
                KsT[(dbase+2)*KSTR + r] = f2tf32(kv.z);
                KsT[(dbase+3)*KSTR + r] = f2tf32(kv.w);
            }
        }
        #pragma unroll
        for (int rep = 0; rep < 8; rep++) {
            int idx = rep * 256 + tid;
            int r   = idx >> 5;
            int dc  = (idx & 31) << 2;
            float4 vv = *(const float4*)(vbase + (size_t)(j0 + r) * (NHKV * HD) + dc);
            unsigned* dst = Vs + r * VSTR + dc;
            dst[0] = f2tf32(vv.x); dst[1] = f2tf32(vv.y);
            dst[2] = f2tf32(vv.z); dst[3] = f2tf32(vv.w);
        }
        __syncthreads();

        float sacc[8][4] = {};
        #pragma unroll
        for (int kc = 0; kc < 16; kc++) {
            int kb = kc << 3;
            unsigned qa[4];
            qa[0] = Qs[(mrow + g    ) * QSTR + kb + t];
            qa[1] = Qs[(mrow + g + 8) * QSTR + kb + t];
            qa[2] = Qs[(mrow + g    ) * QSTR + kb + t + 4];
            qa[3] = Qs[(mrow + g + 8) * QSTR + kb + t + 4];
            unsigned bb[8][2];
            #pragma unroll
            for (int ni = 0; ni < 8; ni++) {
                bb[ni][0] = KsT[(kb + t    ) * KSTR + (ni << 3) + g];
                bb[ni][1] = KsT[(kb + t + 4) * KSTR + (ni << 3) + g];
            }
            #pragma unroll
            for (int ni = 0; ni < 8; ni++)
                mma_tf32(sacc[ni], qa, bb[ni]);
        }

        float mx_lo = -1e30f, mx_hi = -1e30f;
        #pragma unroll
        for (int ni = 0; ni < 8; ni++) {
            int c0 = j0 + (ni << 3) + (t << 1);
            int c1 = c0 + 1;
            if (!((c0 <= qi_lo) && (c0 > qi_lo - WIN))) sacc[ni][0] = -1e30f;
            if (!((c1 <= qi_lo) && (c1 > qi_lo - WIN))) sacc[ni][1] = -1e30f;
            if (!((c0 <= qi_hi) && (c0 > qi_hi - WIN))) sacc[ni][2] = -1e30f;
            if (!((c1 <= qi_hi) && (c1 > qi_hi - WIN))) sacc[ni][3] = -1e30f;
            mx_lo = fmaxf(mx_lo, fmaxf(sacc[ni][0], sacc[ni][1]));
            mx_hi = fmaxf(mx_hi, fmaxf(sacc[ni][2], sacc[ni][3]));
        }
        mx_lo = fmaxf(mx_lo, __shfl_xor_sync(0xffffffffu, mx_lo, 1));
        mx_lo = fmaxf(mx_lo, __shfl_xor_sync(0xffffffffu, mx_lo, 2));
        mx_hi = fmaxf(mx_hi, __shfl_xor_sync(0xffffffffu, mx_hi, 1));
        mx_hi = fmaxf(mx_hi, __shfl_xor_sync(0xffffffffu, mx_hi, 2));

        float mnl = fmaxf(m_lo, mx_lo);
        float mnh = fmaxf(m_hi, mx_hi);
        float cl  = __expf(m_lo - mnl);
        float ch  = __expf(m_hi - mnh);
        m_lo = mnl; m_hi = mnh;

        float ps_lo = 0.f, ps_hi = 0.f;
        unsigned pf[8][4];
        #pragma unroll
        for (int ni = 0; ni < 8; ni++) {
            float p0 = (sacc[ni][0] > -1e29f) ? __expf(sacc[ni][0] - mnl) : 0.f;
            float p1 = (sacc[ni][1] > -1e29f) ? __expf(sacc[ni][1] - mnl) : 0.f;
            float p2 = (sacc[ni][2] > -1e29f) ? __expf(sacc[ni][2] - mnh) : 0.f;
            float p3 = (sacc[ni][3] > -1e29f) ? __expf(sacc[ni][3] - mnh) : 0.f;
            ps_lo += p0 + p1;
            ps_hi += p2 + p3;
            pf[ni][0] = f2tf32(p0); pf[ni][1] = f2tf32(p1);
            pf[ni][2] = f2tf32(p2); pf[ni][3] = f2tf32(p3);
        }
        ps_lo += __shfl_xor_sync(0xffffffffu, ps_lo, 1);
        ps_lo += __shfl_xor_sync(0xffffffffu, ps_lo, 2);
        ps_hi += __shfl_xor_sync(0xffffffffu, ps_hi, 1);
        ps_hi += __shfl_xor_sync(0xffffffffu, ps_hi, 2);
        l_lo = l_lo * cl + ps_lo;
        l_hi = l_hi * ch + ps_hi;

        #pragma unroll
        for (int n2 = 0; n2 < 16; n2++) {
            oacc[n2][0] *= cl; oacc[n2][1] *= cl;
            oacc[n2][2] *= ch; oacc[n2][3] *= ch;
        }

        #pragma unroll
        for (int kc = 0; kc < 8; kc++) {
            unsigned e0 = __shfl_sync(0xffffffffu, pf[kc][0], src0);
            unsigned o0 = __shfl_sync(0xffffffffu, pf[kc][1], src0);
            unsigned e1 = __shfl_sync(0xffffffffu, pf[kc][0], src1);
            unsigned o1 = __shfl_sync(0xffffffffu, pf[kc][1], src1);
            unsigned e2 = __shfl_sync(0xffffffffu, pf[kc][2], src0);
            unsigned o2 = __shfl_sync(0xffffffffu, pf[kc][3], src0);
            unsigned e3 = __shfl_sync(0xffffffffu, pf[kc][2], src1);
            unsigned o3 = __shfl_sync(0xffffffffu, pf[kc][3], src1);
            unsigned af[4];
            af[0] = odd ? o0 : e0;
            af[1] = odd ? o2 : e2;
            af[2] = odd ? o1 : e1;
            af[3] = odd ? o3 : e3;
            int kb = kc << 3;
            #pragma unroll
            for (int n2 = 0; n2 < 16; n2++) {
                unsigned bb2[2];
                bb2[0] = Vs[(kb + t    ) * VSTR + (n2 << 3) + g];
                bb2[1] = Vs[(kb + t + 4) * VSTR + (n2 << 3) + g];
                mma_tf32(oacc[n2], af, bb2);
            }
        }
    }

    float il = 1.0f / l_lo;
    float ih = 1.0f / l_hi;
    float* obase = o + (size_t)b * SEQ * (NHQ * HD) + h * HD;
    int rlo = q0 + mrow + g;
    int rhi = rlo + 8;
    #pragma unroll
    for (int n2 = 0; n2 < 16; n2++) {
        int dn = (n2 << 3) + (t << 1);
        *(float2*)(obase + (size_t)rlo * (NHQ * HD) + dn) =
            make_float2(oacc[n2][0] * il, oacc[n2][1] * il);
        *(float2*)(obase + (size_t)rhi * (NHQ * HD) + dn) =
            make_float2(oacc[n2][2] * ih, oacc[n2][3] * ih);
    }
}

// ---------------------------------------------------------------------------
extern "C" void kernel_launch(void* const* d_in, const int* in_sizes, int n_in,
                              void* d_out, int out_size)
{
    const float* hidden = (const float*)d_in[0];
    const float* wq = (const float*)d_in[1];
    const float* wk = (const float*)d_in[2];
    const float* wv = (const float*)d_in[3];
    const float* wo = (const float*)d_in[4];
    const float* qw = (const float*)d_in[5];
    const float* kw = (const float*)d_in[6];
    float* out = (float*)d_out;

    float *q, *k, *v, *attn, *ct, *st;
    cudaGetSymbolAddress((void**)&q,    g_q);
    cudaGetSymbolAddress((void**)&k,    g_k);
    cudaGetSymbolAddress((void**)&v,    g_v);
    cudaGetSymbolAddress((void**)&attn, g_attn);
    cudaGetSymbolAddress((void**)&ct,   g_rope_cos);
    cudaGetSymbolAddress((void**)&st,   g_rope_sin);
    __nv_bfloat16 *hh, *hl, *qh, *ql, *kh, *kl, *vh, *vl, *oh, *ol, *ah, *al;
    cudaGetSymbolAddress((void**)&hh, g_h_hi);  cudaGetSymbolAddress((void**)&hl, g_h_lo);
    cudaGetSymbolAddress((void**)&qh, g_wq_hi); cudaGetSymbolAddress((void**)&ql, g_wq_lo);
    cudaGetSymbolAddress((void**)&kh, g_wk_hi); cudaGetSymbolAddress((void**)&kl, g_wk_lo);
    cudaGetSymbolAddress((void**)&vh, g_wv_hi); cudaGetSymbolAddress((void**)&vl, g_wv_lo);
    cudaGetSymbolAddress((void**)&oh, g_wo_hi); cudaGetSymbolAddress((void**)&ol, g_wo_lo);
    cudaGetSymbolAddress((void**)&ah, g_at_hi); cudaGetSymbolAddress((void**)&al, g_at_lo);

    cudaFuncSetAttribute(flash_tf32, cudaFuncAttributeMaxDynamicSharedMemorySize,
                         FLASH_BYTES);
    cudaFuncSetAttribute(gemm_qkv, cudaFuncAttributeMaxDynamicSharedMemorySize,
                         GEMM_SMEM);
    cudaFuncSetAttribute(gemm_o, cudaFuncAttributeMaxDynamicSharedMemorySize,
                         GEMM_SMEM);

    rope_table<<<(SEQ*64 + 255) / 256, 256>>>(ct, st);

    // pre-split inputs
    int nh4 = (MROWS * HID) / 4;
    split_bf16<<<nh4/256, 256>>>((const float4*)hidden, (uint2*)hh, (uint2*)hl, nh4);
    int nq4 = (2048 * 2048) / 4;
    split_bf16<<<nq4/256, 256>>>((const float4*)wq, (uint2*)qh, (uint2*)ql, nq4);
    int nk4 = (1024 * 2048) / 4;
    split_bf16<<<nk4/256, 256>>>((const float4*)wk, (uint2*)kh, (uint2*)kl, nk4);
    split_bf16<<<nk4/256, 256>>>((const float4*)wv, (uint2*)vh, (uint2*)vl, nk4);
    split_bf16<<<nq4/256, 256>>>((const float4*)wo, (uint2*)oh, (uint2*)ol, nq4);

    // fused QKV projection (cp.async 3-stage, pre-split operands)
    gemm_qkv<<<dim3(32, MROWS/128), 256, GEMM_SMEM>>>(hh, hl, qh, ql, kh, kl, vh, vl, q, k, v);

    // fused norm+rope
    {
        int warps = MROWS * (NHQ + NHKV);
        norm_rope_both<<<(warps*32 + 255) / 256, 256>>>(q, qw, k, kw, ct, st);
    }

    // flash attention (R8 frozen)
    flash_tf32<<<dim3(SEQ/FBQ, NHQ, NB), 256, FLASH_BYTES>>>(q, k, v, attn);

    // split attn, then O projection
    int na4 = (MROWS * 2048) / 4;
    split_bf16<<<na4/256, 256>>>((const float4*)attn, (uint2*)ah, (uint2*)al, na4);
    gemm_o<<<dim3(HID/128, MROWS/128), 256, GEMM_SMEM>>>(ah, al, oh, ol, out);
}

// round 16
// speedup vs baseline: 1.1811x; 1.1249x over previous
#include <cuda_runtime.h>
#include <cuda_bf16.h>
#include <math.h>

#define NB 2
#define SEQ 2048
#define HID 2048
#define NHQ 16
#define NHKV 8
#define HD 128
#define WIN 1024
#define MROWS (NB*SEQ)   // 4096

// ---------------- scratch (static device globals; no cudaMalloc allowed) ----
__device__ float g_q[(size_t)MROWS * NHQ * HD];
__device__ float g_k[(size_t)MROWS * NHKV * HD];
__device__ float g_v[(size_t)MROWS * NHKV * HD];
__device__ float g_attn[(size_t)MROWS * NHQ * HD];
__device__ float g_rope_cos[SEQ * 64];
__device__ float g_rope_sin[SEQ * 64];

// ---------------------------------------------------------------------------
__global__ void rope_table(float* __restrict__ ct, float* __restrict__ st)
{
    int idx = blockIdx.x * 256 + threadIdx.x;
    if (idx >= SEQ * 64) return;
    int pos = idx >> 6;
    int d   = idx & 63;
    double ang = (double)pos * pow(10000.0, -(double)d / 64.0);
    double s, c;
    sincos(ang, &s, &c);
    ct[idx] = (float)c;
    st[idx] = (float)s;
}

// ---------------------------------------------------------------------------
// helpers
// ---------------------------------------------------------------------------
__device__ __forceinline__ unsigned f2tf32(float x) {
    unsigned r;
    asm("cvt.rna.tf32.f32 %0, %1;" : "=r"(r) : "f"(x));
    return r;
}

__device__ __forceinline__ void mma_tf32(float c[4], const unsigned a[4],
                                         const unsigned b[2]) {
    asm volatile(
        "mma.sync.aligned.m16n8k8.row.col.f32.tf32.tf32.f32 "
        "{%0,%1,%2,%3}, {%4,%5,%6,%7}, {%8,%9}, {%0,%1,%2,%3};\n"
        : "+f"(c[0]), "+f"(c[1]), "+f"(c[2]), "+f"(c[3])
        : "r"(a[0]), "r"(a[1]), "r"(a[2]), "r"(a[3]), "r"(b[0]), "r"(b[1]));
}

__device__ __forceinline__ void mma_bf16(float c[4], const unsigned a[4],
                                         unsigned b0, unsigned b1) {
    asm volatile(
        "mma.sync.aligned.m16n8k16.row.col.f32.bf16.bf16.f32 "
        "{%0,%1,%2,%3}, {%4,%5,%6,%7}, {%8,%9}, {%0,%1,%2,%3};\n"
        : "+f"(c[0]), "+f"(c[1]), "+f"(c[2]), "+f"(c[3])
        : "r"(a[0]), "r"(a[1]), "r"(a[2]), "r"(a[3]), "r"(b0), "r"(b1));
}

__device__ __forceinline__ void ldsm4(unsigned r[4], unsigned addr) {
    asm volatile("ldmatrix.sync.aligned.m8n8.x4.shared.b16 {%0,%1,%2,%3}, [%4];"
        : "=r"(r[0]), "=r"(r[1]), "=r"(r[2]), "=r"(r[3]) : "r"(addr));
}

__device__ __forceinline__ unsigned pack_bf16(float a, float b) {
    unsigned r;
    asm("cvt.rn.bf16x2.f32 %0, %2, %1;" : "=r"(r) : "f"(a), "f"(b));
    return r;
}
__device__ __forceinline__ float trunc_hi(float x) {
    return __uint_as_float(__float_as_uint(x) & 0xFFFF0000u);
}

// ---------------------------------------------------------------------------
// bf16 split-precision GEMM core (validated R7). Used by both the fused QKV
// kernel and the O-projection kernel.
// ---------------------------------------------------------------------------
#define RSTR 48
#define TILE_B (128 * RSTR)
#define STG_B  (4 * TILE_B)
#define GEMM_SMEM (2 * STG_B)   // 49152

__device__ __forceinline__ void gemm_core(
    const float* __restrict__ A, const float* __restrict__ Wt,
    float* __restrict__ C, int m0, int n0, int N, int K, char* gsm)
{
    unsigned sb;
    asm("{ .reg .u64 t; cvta.to.shared.u64 t, %1; cvt.u32.u64 %0, t; }"
        : "=r"(sb) : "l"(gsm));

    const int tid  = threadIdx.x;
    const int lane = tid & 31;
    const int warp = tid >> 5;
    const int wm = warp >> 1;
    const int wn = warp & 1;
    const int t  = lane & 3;

    const int lrow = tid >> 1;
    const int lhal = tid & 1;
    const float* Ag = A  + (size_t)(m0 + lrow) * K + (lhal << 3);
    const float* Wg = Wt + (size_t)(n0 + lrow) * K + (lhal << 3);
    const unsigned sts_off = (unsigned)(lrow * RSTR + (lhal << 4));

    const int sub = lane >> 3;
    const int rin = lane & 7;
    const unsigned a_off = (unsigned)(((sub & 1) * 8 + rin) * RSTR + (sub >> 1) * 16);
    const unsigned b_off = (unsigned)(((sub >> 1) * 8 + rin) * RSTR + (sub & 1) * 16);

    float acc[2][8][4] = {};
    const int nIter = K >> 4;

    float4 ra0, ra1, rb0, rb1;
    ra0 = *(const float4*)(Ag);     ra1 = *(const float4*)(Ag + 4);
    rb0 = *(const float4*)(Wg);     rb1 = *(const float4*)(Wg + 4);

    for (int i = 0; i < nIter; i++) {
        unsigned stgo = (unsigned)(i & 1) * STG_B;
        {
            float a0h = trunc_hi(ra0.x), a1h = trunc_hi(ra0.y);
            float a2h = trunc_hi(ra0.z), a3h = trunc_hi(ra0.w);
            float a4h = trunc_hi(ra1.x), a5h = trunc_hi(ra1.y);
            float a6h = trunc_hi(ra1.z), a7h = trunc_hi(ra1.w);
            uint4 vh = make_uint4(
                __byte_perm(__float_as_uint(ra0.x), __float_as_uint(ra0.y), 0x7632),
                __byte_perm(__float_as_uint(ra0.z), __float_as_uint(ra0.w), 0x7632),
                __byte_perm(__float_as_uint(ra1.x), __float_as_uint(ra1.y), 0x7632),
                __byte_perm(__float_as_uint(ra1.z), __float_as_uint(ra1.w), 0x7632));
            uint4 vl = make_uint4(
                pack_bf16(ra0.x - a0h, ra0.y - a1h),
                pack_bf16(ra0.z - a2h, ra0.w - a3h),
                pack_bf16(ra1.x - a4h, ra1.y - a5h),
                pack_bf16(ra1.z - a6h, ra1.w - a7h));
            *(uint4*)(gsm + stgo + sts_off)          = vh;
            *(uint4*)(gsm + stgo + TILE_B + sts_off) = vl;
            float b0h = trunc_hi(rb0.x), b1h = trunc_hi(rb0.y);
            float b2h = trunc_hi(rb0.z), b3h = trunc_hi(rb0.w);
            float b4h = trunc_hi(rb1.x), b5h = trunc_hi(rb1.y);
            float b6h = trunc_hi(rb1.z), b7h = trunc_hi(rb1.w);
            uint4 wh = make_uint4(
                __byte_perm(__float_as_uint(rb0.x), __float_as_uint(rb0.y), 0x7632),
                __byte_perm(__float_as_uint(rb0.z), __float_as_uint(rb0.w), 0x7632),
                __byte_perm(__float_as_uint(rb1.x), __float_as_uint(rb1.y), 0x7632),
                __byte_perm(__float_as_uint(rb1.z), __float_as_uint(rb1.w), 0x7632));
            uint4 wl = make_uint4(
                pack_bf16(rb0.x - b0h, rb0.y - b1h),
                pack_bf16(rb0.z - b2h, rb0.w - b3h),
                pack_bf16(rb1.x - b4h, rb1.y - b5h),
                pack_bf16(rb1.z - b6h, rb1.w - b7h));
            *(uint4*)(gsm + stgo + 2*TILE_B + sts_off) = wh;
            *(uint4*)(gsm + stgo + 3*TILE_B + sts_off) = wl;
        }
        if (i + 1 < nIter) {
            int k0 = (i + 1) << 4;
            ra0 = *(const float4*)(Ag + k0);  ra1 = *(const float4*)(Ag + k0 + 4);
            rb0 = *(const float4*)(Wg + k0);  rb1 = *(const float4*)(Wg + k0 + 4);
        }
        __syncthreads();

        unsigned stg = sb + stgo;
        unsigned Ahi_b = stg + (unsigned)((wm << 5) * RSTR);
        unsigned Alo_b = Ahi_b + TILE_B;
        unsigned Bhi_b = stg + 2*TILE_B + (unsigned)((wn << 6) * RSTR);
        unsigned Blo_b = Bhi_b + TILE_B;

        unsigned ah[2][4], bh[4][4];
        #pragma unroll
        for (int mi = 0; mi < 2; mi++)
            ldsm4(ah[mi], Ahi_b + (unsigned)((mi << 4) * RSTR) + a_off);
        #pragma unroll
        for (int p = 0; p < 4; p++)
            ldsm4(bh[p], Bhi_b + (unsigned)((p << 4) * RSTR) + b_off);
        #pragma unroll
        for (int mi = 0; mi < 2; mi++)
            #pragma unroll
            for (int p = 0; p < 4; p++) {
                mma_bf16(acc[mi][(p<<1)  ], ah[mi], bh[p][0], bh[p][1]);
                mma_bf16(acc[mi][(p<<1)+1], ah[mi], bh[p][2], bh[p][3]);
            }
        unsigned al[2][4];
        #pragma unroll
        for (int mi = 0; mi < 2; mi++)
            ldsm4(al[mi], Alo_b + (unsigned)((mi << 4) * RSTR) + a_off);
        #pragma unroll
        for (int mi = 0; mi < 2; mi++)
            #pragma unroll
            for (int p = 0; p < 4; p++) {
                mma_bf16(acc[mi][(p<<1)  ], al[mi], bh[p][0], bh[p][1]);
                mma_bf16(acc[mi][(p<<1)+1], al[mi], bh[p][2], bh[p][3]);
            }
        unsigned bl[4][4];
        #pragma unroll
        for (int p = 0; p < 4; p++)
            ldsm4(bl[p], Blo_b + (unsigned)((p << 4) * RSTR) + b_off);
        #pragma unroll
        for (int mi = 0; mi < 2; mi++)
            #pragma unroll
            for (int p = 0; p < 4; p++) {
                mma_bf16(acc[mi][(p<<1)  ], ah[mi], bl[p][0], bl[p][1]);
                mma_bf16(acc[mi][(p<<1)+1], ah[mi], bl[p][2], bl[p][3]);
            }
    }

    const int gid = lane >> 2;
    #pragma unroll
    for (int mi = 0; mi < 2; mi++) {
        int r0 = m0 + (wm << 5) + (mi << 4) + gid;
        #pragma unroll
        for (int ni = 0; ni < 8; ni++) {
            int cc = n0 + (wn << 6) + (ni << 3) + (t << 1);
            *(float2*)(C + (size_t)r0 * N + cc) =
                make_float2(acc[mi][ni][0], acc[mi][ni][1]);
            *(float2*)(C + (size_t)(r0 + 8) * N + cc) =
                make_float2(acc[mi][ni][2], acc[mi][ni][3]);
        }
    }
}

// Fused QKV: grid (32 n-blocks, 32 m-blocks). n 0-15 -> Q, 16-23 -> K, 24-31 -> V.
__global__ __launch_bounds__(256) void gemm_qkv(
    const float* __restrict__ A,
    const float* __restrict__ wq, const float* __restrict__ wk,
    const float* __restrict__ wv,
    float* __restrict__ q, float* __restrict__ k, float* __restrict__ v)
{
    extern __shared__ __align__(16) char gsm[];
    int nb = blockIdx.x;
    int m0 = blockIdx.y << 7;
    const float* Wt; float* C; int N; int n0;
    if (nb < 16)      { Wt = wq; C = q; N = NHQ*HD;  n0 = nb << 7; }
    else if (nb < 24) { Wt = wk; C = k; N = NHKV*HD; n0 = (nb - 16) << 7; }
    else              { Wt = wv; C = v; N = NHKV*HD; n0 = (nb - 24) << 7; }
    gemm_core(A, Wt, C, m0, n0, N, HID, gsm);
}

// O projection
__global__ __launch_bounds__(256) void gemm_o(
    const float* __restrict__ A, const float* __restrict__ Wt,
    float* __restrict__ C)
{
    extern __shared__ __align__(16) char gsm[];
    gemm_core(A, Wt, C, blockIdx.y << 7, blockIdx.x << 7, HID, NHQ*HD, gsm);
}

// ---------------------------------------------------------------------------
// Fused RMSNorm + RoPE for BOTH q and k in one launch.
// ---------------------------------------------------------------------------
__global__ __launch_bounds__(256) void norm_rope_both(
    float* __restrict__ xq, const float* __restrict__ wq,
    float* __restrict__ xk, const float* __restrict__ wk,
    const float* __restrict__ ct, const float* __restrict__ st)
{
    int gw   = (blockIdx.x * 256 + threadIdx.x) >> 5;
    int lane = threadIdx.x & 31;
    float* x; const float* w; int n_heads;
    if (gw < MROWS * NHQ) { x = xq; w = wq; n_heads = NHQ; }
    else { gw -= MROWS * NHQ; if (gw >= MROWS * NHKV) return;
           x = xk; w = wk; n_heads = NHKV; }
    int m = gw / n_heads;
    int h = gw - m * n_heads;
    int pos = m & (SEQ - 1);
    float* row = x + (size_t)m * (n_heads * HD) + h * HD;
    float x0 = row[lane], x1 = row[lane+32], x2 = row[lane+64], x3 = row[lane+96];
    float ss = x0*x0 + x1*x1 + x2*x2 + x3*x3;
    #pragma unroll
    for (int o = 16; o; o >>= 1) ss += __shfl_xor_sync(0xffffffffu, ss, o);
    float rstd = rsqrtf(ss * (1.0f / HD) + 1e-6f);
    float y0 = x0 * rstd * (1.f + w[lane]);
    float y1 = x1 * rstd * (1.f + w[lane+32]);
    float y2 = x2 * rstd * (1.f + w[lane+64]);
    float y3 = x3 * rstd * (1.f + w[lane+96]);
    float c0 = ct[pos*64 + lane],      s0 = st[pos*64 + lane];
    float c1 = ct[pos*64 + lane + 32], s1 = st[pos*64 + lane + 32];
    row[lane]      = y0 * c0 - y2 * s0;
    row[lane+64]   = y2 * c0 + y0 * s0;
    row[lane+32]   = y1 * c1 - y3 * s1;
    row[lane+96]   = y3 * c1 + y1 * s1;
}

// ---------------------------------------------------------------------------
// Flash attention (R8 passing version): BQ=128, register softmax, tf32 mma.
// ---------------------------------------------------------------------------
#define FBQ 128
#define FBK 64
#define QSTR 132
#define KSTR 72
#define VSTR 136
#define FLASH_WORDS (128*QSTR + 128*KSTR + 64*VSTR)
#define FLASH_BYTES (FLASH_WORDS * 4)

__global__ __launch_bounds__(256) void flash_tf32(
    const float* __restrict__ q, const float* __restrict__ k,
    const float* __restrict__ v, float* __restrict__ o)
{
    extern __shared__ unsigned smu[];
    unsigned* Qs  = smu;
    unsigned* KsT = Qs + 128 * QSTR;
    unsigned* Vs  = KsT + 128 * KSTR;

    const int tid  = threadIdx.x;
    const int lane = tid & 31;
    const int warp = tid >> 5;
    const int g    = lane >> 2;
    const int t    = lane & 3;
    const int mrow = warp << 4;

    const int q0 = blockIdx.x * FBQ;
    const int h  = blockIdx.y;
    const int b  = blockIdx.z;
    const int hk = h >> 1;
    const float* qbase = q + (size_t)b * SEQ * (NHQ  * HD) + h  * HD;
    const float* kbase = k + (size_t)b * SEQ * (NHKV * HD) + hk * HD;
    const float* vbase = v + (size_t)b * SEQ * (NHKV * HD) + hk * HD;
    const float scale = 0.08838834764831845f;

    #pragma unroll
    for (int rep = 0; rep < 16; rep++) {
        int idx = rep * 256 + tid;
        int r   = idx >> 5;
        int dc  = (idx & 31) << 2;
        float4 va = *(const float4*)(qbase + (size_t)(q0 + r) * (NHQ * HD) + dc);
        unsigned* dst = Qs + r * QSTR + dc;
        dst[0] = f2tf32(va.x * scale); dst[1] = f2tf32(va.y * scale);
        dst[2] = f2tf32(va.z * scale); dst[3] = f2tf32(va.w * scale);
    }

    float oacc[16][4] = {};
    float m_lo = -1e30f, m_hi = -1e30f, l_lo = 0.f, l_hi = 0.f;
    const int qi_lo = q0 + mrow + g;
    const int qi_hi = qi_lo + 8;

    int jlo = q0 - (WIN - 1); if (jlo < 0) jlo = 0;
    const int jstart = jlo & ~(FBK - 1);

    const int src0 = (lane & ~3) | (t >> 1);
    const int src1 = src0 + 2;
    const bool odd = t & 1;

    for (int j0 = jstart; j0 < q0 + FBQ; j0 += FBK) {
        __syncthreads();
        {
            int r  = tid >> 2;
            int c4 = (tid & 3) << 2;
            #pragma unroll
            for (int sub2 = 0; sub2 < 8; sub2++) {
                float4 kv = *(const float4*)(kbase + (size_t)(j0 + r) * (NHKV * HD) + sub2 * 16 + c4);
                int dbase = sub2 * 16 + c4;
                KsT[(dbase+0)*KSTR + r] = f2tf32(kv.x);
                KsT[(dbase+1)*KSTR + r] = f2tf32(kv.y);
                KsT[(dbase+2)*KSTR + r] = f2tf32(kv.z);
                KsT[(dbase+3)*KSTR + r] = f2tf32(kv.w);
            }
        }
        #pragma unroll
        for (int rep = 0; rep < 8; rep++) {
            int idx = rep * 256 + tid;
            int r   = idx >> 5;
            int dc  = (idx & 31) << 2;
            float4 vv = *(const float4*)(vbase + (size_t)(j0 + r) * (NHKV * HD) + dc);
            unsigned* dst = Vs + r * VSTR + dc;
            dst[0] = f2tf32(vv.x); dst[1] = f2tf32(vv.y);
            dst[2] = f2tf32(vv.z); dst[3] = f2tf32(vv.w);
        }
        __syncthreads();

        float sacc[8][4] = {};
        #pragma unroll
        for (int kc = 0; kc < 16; kc++) {
            int kb = kc << 3;
            unsigned qa[4];
            qa[0] = Qs[(mrow + g    ) * QSTR + kb + t];
            qa[1] = Qs[(mrow + g + 8) * QSTR + kb + t];
            qa[2] = Qs[(mrow + g    ) * QSTR + kb + t + 4];
            qa[3] = Qs[(mrow + g + 8) * QSTR + kb + t + 4];
            unsigned bb[8][2];
            #pragma unroll
            for (int ni = 0; ni < 8; ni++) {
                bb[ni][0] = KsT[(kb + t    ) * KSTR + (ni << 3) + g];
                bb[ni][1] = KsT[(kb + t + 4) * KSTR + (ni << 3) + g];
            }
            #pragma unroll
            for (int ni = 0; ni < 8; ni++)
                mma_tf32(sacc[ni], qa, bb[ni]);
        }

        float mx_lo = -1e30f, mx_hi = -1e30f;
        #pragma unroll
        for (int ni = 0; ni < 8; ni++) {
            int c0 = j0 + (ni << 3) + (t << 1);
            int c1 = c0 + 1;
            if (!((c0 <= qi_lo) && (c0 > qi_lo - WIN))) sacc[ni][0] = -1e30f;
            if (!((c1 <= qi_lo) && (c1 > qi_lo - WIN))) sacc[ni][1] = -1e30f;
            if (!((c0 <= qi_hi) && (c0 > qi_hi - WIN))) sacc[ni][2] = -1e30f;
            if (!((c1 <= qi_hi) && (c1 > qi_hi - WIN))) sacc[ni][3] = -1e30f;
            mx_lo = fmaxf(mx_lo, fmaxf(sacc[ni][0], sacc[ni][1]));
            mx_hi = fmaxf(mx_hi, fmaxf(sacc[ni][2], sacc[ni][3]));
        }
        mx_lo = fmaxf(mx_lo, __shfl_xor_sync(0xffffffffu, mx_lo, 1));
        mx_lo = fmaxf(mx_lo, __shfl_xor_sync(0xffffffffu, mx_lo, 2));
        mx_hi = fmaxf(mx_hi, __shfl_xor_sync(0xffffffffu, mx_hi, 1));
        mx_hi = fmaxf(mx_hi, __shfl_xor_sync(0xffffffffu, mx_hi, 2));

        float mnl = fmaxf(m_lo, mx_lo);
        float mnh = fmaxf(m_hi, mx_hi);
        float cl  = __expf(m_lo - mnl);
        float ch  = __expf(m_hi - mnh);
        m_lo = mnl; m_hi = mnh;

        float ps_lo = 0.f, ps_hi = 0.f;
        unsigned pf[8][4];
        #pragma unroll
        for (int ni = 0; ni < 8; ni++) {
            float p0 = (sacc[ni][0] > -1e29f) ? __expf(sacc[ni][0] - mnl) : 0.f;
            float p1 = (sacc[ni][1] > -1e29f) ? __expf(sacc[ni][1] - mnl) : 0.f;
            float p2 = (sacc[ni][2] > -1e29f) ? __expf(sacc[ni][2] - mnh) : 0.f;
            float p3 = (sacc[ni][3] > -1e29f) ? __expf(sacc[ni][3] - mnh) : 0.f;
            ps_lo += p0 + p1;
            ps_hi += p2 + p3;
            pf[ni][0] = f2tf32(p0); pf[ni][1] = f2tf32(p1);
            pf[ni][2] = f2tf32(p2); pf[ni][3] = f2tf32(p3);
        }
        ps_lo += __shfl_xor_sync(0xffffffffu, ps_lo, 1);
        ps_lo += __shfl_xor_sync(0xffffffffu, ps_lo, 2);
        ps_hi += __shfl_xor_sync(0xffffffffu, ps_hi, 1);
        ps_hi += __shfl_xor_sync(0xffffffffu, ps_hi, 2);
        l_lo = l_lo * cl + ps_lo;
        l_hi = l_hi * ch + ps_hi;

        #pragma unroll
        for (int n2 = 0; n2 < 16; n2++) {
            oacc[n2][0] *= cl; oacc[n2][1] *= cl;
            oacc[n2][2] *= ch; oacc[n2][3] *= ch;
        }

        #pragma unroll
        for (int kc = 0; kc < 8; kc++) {
            unsigned e0 = __shfl_sync(0xffffffffu, pf[kc][0], src0);
            unsigned o0 = __shfl_sync(0xffffffffu, pf[kc][1], src0);
            unsigned e1 = __shfl_sync(0xffffffffu, pf[kc][0], src1);
            unsigned o1 = __shfl_sync(0xffffffffu, pf[kc][1], src1);
            unsigned e2 = __shfl_sync(0xffffffffu, pf[kc][2], src0);
            unsigned o2 = __shfl_sync(0xffffffffu, pf[kc][3], src0);
            unsigned e3 = __shfl_sync(0xffffffffu, pf[kc][2], src1);
            unsigned o3 = __shfl_sync(0xffffffffu, pf[kc][3], src1);
            unsigned af[4];
            af[0] = odd ? o0 : e0;
            af[1] = odd ? o2 : e2;
            af[2] = odd ? o1 : e1;
            af[3] = odd ? o3 : e3;
            int kb = kc << 3;
            #pragma unroll
            for (int n2 = 0; n2 < 16; n2++) {
                unsigned bb2[2];
                bb2[0] = Vs[(kb + t    ) * VSTR + (n2 << 3) + g];
                bb2[1] = Vs[(kb + t + 4) * VSTR + (n2 << 3) + g];
                mma_tf32(oacc[n2], af, bb2);
            }
        }
    }

    float il = 1.0f / l_lo;
    float ih = 1.0f / l_hi;
    float* obase = o + (size_t)b * SEQ * (NHQ * HD) + h * HD;
    int rlo = q0 + mrow + g;
    int rhi = rlo + 8;
    #pragma unroll
    for (int n2 = 0; n2 < 16; n2++) {
        int dn = (n2 << 3) + (t << 1);
        *(float2*)(obase + (size_t)rlo * (NHQ * HD) + dn) =
            make_float2(oacc[n2][0] * il, oacc[n2][1] * il);
        *(float2*)(obase + (size_t)rhi * (NHQ * HD) + dn) =
            make_float2(oacc[n2][2] * ih, oacc[n2][3] * ih);
    }
}

// ---------------------------------------------------------------------------
extern "C" void kernel_launch(void* const* d_in, const int* in_sizes, int n_in,
                              void* d_out, int out_size)
{
    const float* hidden = (const float*)d_in[0];
    const float* wq = (const float*)d_in[1];
    const float* wk = (const float*)d_in[2];
    const float* wv = (const float*)d_in[3];
    const float* wo = (const float*)d_in[4];
    const float* qw = (const float*)d_in[5];
    const float* kw = (const float*)d_in[6];
    float* out = (float*)d_out;

    float *q, *k, *v, *attn, *ct, *st;
    cudaGetSymbolAddress((void**)&q,    g_q);
    cudaGetSymbolAddress((void**)&k,    g_k);
    cudaGetSymbolAddress((void**)&v,    g_v);
    cudaGetSymbolAddress((void**)&attn, g_attn);
    cudaGetSymbolAddress((void**)&ct,   g_rope_cos);
    cudaGetSymbolAddress((void**)&st,   g_rope_sin);

    cudaFuncSetAttribute(flash_tf32, cudaFuncAttributeMaxDynamicSharedMemorySize,
                         FLASH_BYTES);
    cudaFuncSetAttribute(gemm_qkv, cudaFuncAttributeMaxDynamicSharedMemorySize,
                         GEMM_SMEM);
    cudaFuncSetAttribute(gemm_o, cudaFuncAttributeMaxDynamicSharedMemorySize,
                         GEMM_SMEM);

    // launch 0: rope tables
    rope_table<<<(SEQ*64 + 255) / 256, 256>>>(ct, st);
    // launch 1: fused QKV projection
    gemm_qkv<<<dim3(32, MROWS/128), 256, GEMM_SMEM>>>(hidden, wq, wk, wv, q, k, v);
    // launch 2: fused norm+rope for q and k
    {
        int warps = MROWS * (NHQ + NHKV);
        norm_rope_both<<<(warps*32 + 255) / 256, 256>>>(q, qw, k, kw, ct, st);
    }
    // launch 3: flash attention  (profiled slot)
    flash_tf32<<<dim3(SEQ/FBQ, NHQ, NB), 256, FLASH_BYTES>>>(q, k, v, attn);
    // launch 4: output projection
    gemm_o<<<dim3(HID/128, MROWS/128), 256, GEMM_SMEM>>>(attn, wo, out);
}